// round 13
// baseline (speedup 1.0000x reference)
#include <cuda_runtime.h>
#include <cuda_bf16.h>
#include <stddef.h>

#define S_LEN 16384
#define T_TAGS 1024
#define BEAM 64
#define NSTEP (S_LEN - 1)      // 16383
#define CH_L 128
#define NCH 128

// ---------------- scratch (device globals: no allocation allowed) ----------------
__device__ float         g_bsc[S_LEN * BEAM];          // top-64 scores per row (jax order)
__device__ int           g_btag[S_LEN * BEAM];         // top-64 tag indices per row
__device__ float         g_Wseq[NSTEP * BEAM * BEAM];  // 268MB: Wseq[i][c][p] = weights[pt_i[p]][ct_i[c]]
__device__ unsigned char g_bps[NSTEP * BEAM];          // backpointers
__device__ unsigned char g_allmap[NSTEP * BEAM];       // per-step composed backtrack maps
__device__ float         g_vit[BEAM];
__device__ float         g_fwd[BEAM];
__device__ unsigned char g_Barr[NCH];                  // chunk-boundary best indices
__device__ float         g_logZ;
__device__ float         g_partials[64];

// monotonic float<->uint mapping (total order identical to float order; no NaNs present)
__device__ __forceinline__ unsigned fmap(float x) {
    unsigned u = __float_as_uint(x);
    return u ^ (((unsigned)((int)u >> 31)) | 0x80000000u);
}
__device__ __forceinline__ float funmap(unsigned m) {
    unsigned s = (m & 0x80000000u) ? 0x80000000u : 0xFFFFFFFFu;
    return __uint_as_float(m ^ s);
}

// ---------------- Phase 1: exact top-64 per row, jax ordering (bitonic) ----------------
__global__ void __launch_bounds__(512) topk_kernel(const float* __restrict__ scores) {
    __shared__ unsigned long long keys[T_TAGS];
    int row = blockIdx.x;
    const float* rp = scores + (size_t)row * T_TAGS;
    int tid = threadIdx.x;
    for (int e = tid; e < T_TAGS; e += 512) {
        unsigned u = fmap(rp[e]);
        // key ascending == (value descending, index ascending) -> matches jax.lax.top_k
        keys[e] = ((unsigned long long)(~u) << 32) | (unsigned)e;
    }
    __syncthreads();
    for (int k = 2; k <= T_TAGS; k <<= 1) {
        for (int j = k >> 1; j > 0; j >>= 1) {
            #pragma unroll
            for (int r = 0; r < 2; ++r) {
                int i = tid + r * 512;
                int ixj = i ^ j;
                if (ixj > i) {
                    unsigned long long a = keys[i], b = keys[ixj];
                    bool up = ((i & k) == 0);
                    if ((a > b) == up) { keys[i] = b; keys[ixj] = a; }
                }
            }
            __syncthreads();
        }
    }
    if (tid < BEAM) {
        unsigned long long kk = keys[tid];
        int idx = (int)(kk & 0xffffffffu);
        g_btag[row * BEAM + tid] = idx;
        g_bsc[row * BEAM + tid]  = rp[idx];   // exact original value
    }
}

// ---------------- Phase 2: pre-gather transition matrices (full chip) ----------------
__global__ void __launch_bounds__(256) gather_kernel(const float* __restrict__ weights) {
    __shared__ int pt[BEAM], ct[BEAM];
    int i = blockIdx.x;                 // step 0..NSTEP-1
    int tid = threadIdx.x;
    if (tid < BEAM)           pt[tid]       = g_btag[i * BEAM + tid];
    else if (tid < 2 * BEAM)  ct[tid - 64]  = g_btag[(i + 1) * BEAM + (tid - 64)];
    __syncthreads();
    float* out = g_Wseq + (size_t)i * (BEAM * BEAM);
    #pragma unroll 4
    for (int e = tid; e < BEAM * BEAM; e += 256) {
        int c = e >> 6, p = e & 63;
        out[e] = weights[(size_t)pt[p] * T_TAGS + ct[c]];
    }
}

// ---------------- Phase 3: sequential scan (single persistent CTA) ----------------
__device__ __forceinline__ void scan_step(
    int i, float2 W0, float2 W1, float cs0, float cs1,
    const float* vin, const float* fin, float* vout_s, float* fout_s,
    int c0, int c1, int p0, int p1, int l)
{
    const unsigned FULL = 0xffffffffu;
    float2 vv = *(const float2*)(vin + p0);
    float2 ff = *(const float2*)(fin + p0);

    // Viterbi: exact rounding (vit + cur_s) + w as in reference
    float v00 = __fadd_rn(__fadd_rn(vv.x, cs0), W0.x);
    float v01 = __fadd_rn(__fadd_rn(vv.y, cs0), W0.y);
    float v10 = __fadd_rn(__fadd_rn(vv.x, cs1), W1.x);
    float v11 = __fadd_rn(__fadd_rn(vv.y, cs1), W1.y);
    unsigned u00 = fmap(v00), u01 = fmap(v01), u10 = fmap(v10), u11 = fmap(v11);
    unsigned pu0; int pi0;
    if (u01 > u00) { pu0 = u01; pi0 = p1; } else { pu0 = u00; pi0 = p0; }   // tie -> lower p
    unsigned pu1; int pi1;
    if (u11 > u10) { pu1 = u11; pi1 = p1; } else { pu1 = u10; pi1 = p0; }

    unsigned m0 = __reduce_max_sync(FULL, pu0);
    unsigned m1 = __reduce_max_sync(FULL, pu1);
    unsigned b0 = __ballot_sync(FULL, pu0 == m0);
    unsigned b1 = __ballot_sync(FULL, pu1 == m1);
    int bp0 = __shfl_sync(FULL, pi0, __ffs((int)b0) - 1);   // lowest lane -> lowest p (first-index argmax)
    int bp1 = __shfl_sync(FULL, pi1, __ffs((int)b1) - 1);

    // forward: logsumexp (tolerance is loose; fast intrinsics fine)
    float f00 = __fadd_rn(__fadd_rn(ff.x, cs0), W0.x);
    float f01 = __fadd_rn(__fadd_rn(ff.y, cs0), W0.y);
    float f10 = __fadd_rn(__fadd_rn(ff.x, cs1), W1.x);
    float f11 = __fadd_rn(__fadd_rn(ff.y, cs1), W1.y);
    unsigned fq0 = fmap(f00), fq1 = fmap(f01);
    unsigned fr0 = fmap(f10), fr1 = fmap(f11);
    unsigned fu0 = fq0 > fq1 ? fq0 : fq1;
    unsigned fu1 = fr0 > fr1 ? fr0 : fr1;
    float fm0 = funmap(__reduce_max_sync(FULL, fu0));
    float fm1 = funmap(__reduce_max_sync(FULL, fu1));
    float s0 = __expf(f00 - fm0) + __expf(f01 - fm0);
    float s1 = __expf(f10 - fm1) + __expf(f11 - fm1);
    #pragma unroll
    for (int o = 16; o; o >>= 1) {
        s0 += __shfl_xor_sync(FULL, s0, o);
        s1 += __shfl_xor_sync(FULL, s1, o);
    }
    float nf0 = fm0 + __logf(s0);
    float nf1 = fm1 + __logf(s1);
    float nv0 = funmap(m0), nv1 = funmap(m1);

    if (l == 0) {
        vout_s[c0] = nv0; fout_s[c0] = nf0;
        g_bps[(size_t)i * BEAM + c0] = (unsigned char)bp0;
    } else if (l == 1) {
        vout_s[c1] = nv1; fout_s[c1] = nf1;
        g_bps[(size_t)i * BEAM + c1] = (unsigned char)bp1;
    }
    __syncthreads();
}

__global__ void __launch_bounds__(1024, 1) scan_kernel() {
    __shared__ float svit[2][BEAM];
    __shared__ float sfwd[2][BEAM];
    int tid = threadIdx.x;
    int w = tid >> 5, l = tid & 31;
    int c0 = 2 * w, c1 = c0 + 1;
    int p0 = 2 * l, p1 = p0 + 1;

    if (tid < BEAM) { float v = g_bsc[tid]; svit[0][tid] = v; sfwd[0][tid] = v; }
    __syncthreads();

    // depth-2 register prefetch of Wseq + cur_s (addresses independent of carry)
    float2 Wa0, Wa1, Wb0, Wb1; float csa0, csa1, csb0, csb1;
    {
        const float* Wr = g_Wseq;
        Wa0 = *(const float2*)(Wr + c0 * 64 + p0);
        Wa1 = *(const float2*)(Wr + c1 * 64 + p0);
        csa0 = g_bsc[1 * BEAM + c0]; csa1 = g_bsc[1 * BEAM + c1];
        Wr = g_Wseq + 4096;
        Wb0 = *(const float2*)(Wr + c0 * 64 + p0);
        Wb1 = *(const float2*)(Wr + c1 * 64 + p0);
        csb0 = g_bsc[2 * BEAM + c0]; csb1 = g_bsc[2 * BEAM + c1];
    }

    int i = 0;
    while (i < NSTEP) {
        { // even step: reads buf0, writes buf1
            float2 W0 = Wa0, W1 = Wa1; float cc0 = csa0, cc1 = csa1;
            int pf = i + 2;
            if (pf < NSTEP) {
                const float* Wr = g_Wseq + (size_t)pf * 4096;
                Wa0 = *(const float2*)(Wr + c0 * 64 + p0);
                Wa1 = *(const float2*)(Wr + c1 * 64 + p0);
                csa0 = g_bsc[(pf + 1) * BEAM + c0];
                csa1 = g_bsc[(pf + 1) * BEAM + c1];
            }
            scan_step(i, W0, W1, cc0, cc1, svit[0], sfwd[0], svit[1], sfwd[1], c0, c1, p0, p1, l);
            ++i;
        }
        if (i >= NSTEP) break;
        { // odd step: reads buf1, writes buf0
            float2 W0 = Wb0, W1 = Wb1; float cc0 = csb0, cc1 = csb1;
            int pf = i + 2;
            if (pf < NSTEP) {
                const float* Wr = g_Wseq + (size_t)pf * 4096;
                Wb0 = *(const float2*)(Wr + c0 * 64 + p0);
                Wb1 = *(const float2*)(Wr + c1 * 64 + p0);
                csb0 = g_bsc[(pf + 1) * BEAM + c0];
                csb1 = g_bsc[(pf + 1) * BEAM + c1];
            }
            scan_step(i, W0, W1, cc0, cc1, svit[1], sfwd[1], svit[0], sfwd[0], c0, c1, p0, p1, l);
            ++i;
        }
    }
    // NSTEP is odd -> final state in buffer 1
    if (tid < BEAM) { g_vit[tid] = svit[NSTEP & 1][tid]; g_fwd[tid] = sfwd[NSTEP & 1][tid]; }
}

// ---------------- Phase 4: parallel backtrack (chunked map composition) ----------------
__global__ void __launch_bounds__(64) chunkmap_kernel() {
    __shared__ unsigned char sbp[CH_L * BEAM];
    int j = blockIdx.x;
    int lo = j * CH_L;
    int hi = min(lo + CH_L, NSTEP);
    int n = hi - lo;
    int tid = threadIdx.x;   // = column c at time hi
    for (int e = tid; e < n * BEAM; e += 64) sbp[e] = g_bps[(size_t)lo * BEAM + e];
    __syncthreads();
    int m = tid;
    for (int ii = n - 1; ii >= 0; --ii) {
        m = sbp[ii * BEAM + m];
        g_allmap[(size_t)(lo + ii) * BEAM + tid] = (unsigned char)m;
    }
}

__global__ void finish_kernel() {
    if (threadIdx.x != 0 || blockIdx.x != 0) return;
    // last = first-index argmax of final vit
    float best = g_vit[0]; int last = 0;
    for (int c = 1; c < BEAM; ++c) { float v = g_vit[c]; if (v > best) { best = v; last = c; } }
    int b = last;
    g_Barr[NCH - 1] = (unsigned char)b;           // index at time S-1 (= end of last chunk)
    for (int j = NCH - 1; j >= 1; --j) {
        b = g_allmap[(size_t)(j * CH_L) * BEAM + b];
        g_Barr[j - 1] = (unsigned char)b;          // index at time j*CH_L (= end of chunk j-1)
    }
    // logZ = logsumexp(final fwd)
    float mx = g_fwd[0];
    for (int c = 1; c < BEAM; ++c) mx = fmaxf(mx, g_fwd[c]);
    float s = 0.f;
    for (int c = 0; c < BEAM; ++c) s += __expf(g_fwd[c] - mx);
    g_logZ = mx + __logf(s);
}

__global__ void __launch_bounds__(256) emit_kernel(float* __restrict__ out) {
    int s = blockIdx.x * 256 + threadIdx.x;
    if (s >= S_LEN) return;
    int bi;
    if (s == S_LEN - 1) bi = g_Barr[NCH - 1];
    else                bi = g_allmap[(size_t)s * BEAM + g_Barr[s >> 7]];
    out[s] = (float)g_btag[s * BEAM + bi];
}

// ---------------- Phase 5: deterministic base+crf partial sums ----------------
__global__ void __launch_bounds__(256) partial_kernel(const float* __restrict__ scores,
                                                      const float* __restrict__ weights,
                                                      const int* __restrict__ tags) {
    __shared__ float red[256];
    int s = blockIdx.x * 256 + threadIdx.x;    // 64 blocks * 256 = 16384 exactly
    int t0 = tags[s];
    float acc = scores[(size_t)s * T_TAGS + t0];
    if (s < S_LEN - 1) acc += weights[(size_t)t0 * T_TAGS + tags[s + 1]];
    red[threadIdx.x] = acc;
    __syncthreads();
    for (int o = 128; o; o >>= 1) {
        if (threadIdx.x < o) red[threadIdx.x] += red[threadIdx.x + o];
        __syncthreads();
    }
    if (threadIdx.x == 0) g_partials[blockIdx.x] = red[0];
}

__global__ void final2_kernel(float* __restrict__ out) {
    if (threadIdx.x != 0 || blockIdx.x != 0) return;
    float t = 0.f;
    for (int b = 0; b < 64; ++b) t += g_partials[b];
    out[S_LEN] = g_logZ - t;    // -logprob = logZ - base - crf
}

// ---------------- launcher ----------------
extern "C" void kernel_launch(void* const* d_in, const int* in_sizes, int n_in,
                              void* d_out, int out_size) {
    const float* scores  = (const float*)d_in[0];
    const float* weights = (const float*)d_in[1];
    const int*   tags    = (const int*)d_in[2];
    float* out = (float*)d_out;

    topk_kernel<<<S_LEN, 512>>>(scores);
    gather_kernel<<<NSTEP, 256>>>(weights);
    scan_kernel<<<1, 1024>>>();
    chunkmap_kernel<<<NCH, 64>>>();
    finish_kernel<<<1, 32>>>();
    emit_kernel<<<(S_LEN + 255) / 256, 256>>>(out);
    partial_kernel<<<64, 256>>>(scores, weights, tags);
    final2_kernel<<<1, 32>>>(out);
}